// round 1
// baseline (speedup 1.0000x reference)
#include <cuda_runtime.h>
#include <cstdint>
#include <cstddef>

#define NFEAT 17
#define HDIM 8
#define BSZ 256
#define TSTEPS 512
#define XDIM 59
#define CHK 32
#define NCHK (TSTEPS/CHK)
#define BPC 2
#define NTHREADS 288
#define ROWPAD (CHK*XDIM + 16)   // pad so xp[d] overreads stay in-array

// Chain-to-slot mapping. slot = warp*4 + group. Heavy-d features (f1..f4)
// are packed into warps 1 and 2 (SMSP1/SMSP2); SMSP0 (warps 0,4,8) gets only
// d=1 features so the 3-warp subpartition carries the lightest per-step load.
__device__ __constant__ int8_t c_slot_f[36] = {
   6, 6, 7, 7,   3, 2, 4, 1,   3, 2, 4, 1,   0, 0, 5, 5,
   8, 8, 9, 9,  12,12,13,13,  14,14,15,15,  16,16,16,16,  10,10,11,11};
__device__ __constant__ int8_t c_slot_b[36] = {
   0, 1, 0, 1,   0, 0, 0, 0,   1, 1, 1, 1,   0, 1, 0, 1,
   0, 1, 0, 1,   0, 1, 0, 1,   0, 1, 0, 1,   0, 1, 0, 1,   0, 1, 0, 1};
__device__ __constant__ int8_t c_slot_wr[36] = {
   1, 1, 1, 1,   1, 1, 1, 1,   1, 1, 1, 1,   1, 1, 1, 1,
   1, 1, 1, 1,   1, 1, 1, 1,   1, 1, 1, 1,   1, 1, 0, 0,   1, 1, 1, 1};
// per-warp max feature dim (warp-uniform gx loop bound; W_ih is zero-masked
// beyond each feature's true d so extra iterations are exact no-ops)
__device__ __constant__ int8_t c_warp_mdw[9] = {1,13,13,2,1,1,1,1,1};
// segment start offsets (cumsum of DIMS)
__device__ __constant__ int8_t c_start[17] =
  {0,2,10,22,35,47,48,49,50,51,52,53,54,55,56,57,58};

__device__ __forceinline__ void cp16(uint32_t s, const float* g){
  asm volatile("cp.async.ca.shared.global [%0], [%1], 16;" :: "r"(s), "l"(g) : "memory");
}

extern "C" __global__ void __launch_bounds__(NTHREADS, 1)
mcgru_kernel(const float* __restrict__ x,   const float* __restrict__ Wih,
             const float* __restrict__ Whh, const float* __restrict__ bih,
             const float* __restrict__ bhh, float* __restrict__ out)
{
  __shared__ __align__(16) float xs[2][BPC][ROWPAD];

  const int tid  = threadIdx.x;
  const int w    = tid >> 5;
  const int slot = tid >> 3;
  const int j    = tid & 7;
  const int f    = c_slot_f[slot];
  const int bl   = c_slot_b[slot];
  const bool wen = (bool)c_slot_wr[slot];
  const int mdw  = c_warp_mdw[w];
  const int startf = c_start[f];
  const int bg0  = blockIdx.x * BPC;

  // ---- per-thread weights in registers (rows j, 8+j, 16+j of feature f) ----
  float wr_[13], wz_[13], wn_[13];
  {
    const float* Wf = Wih + f*24*13;
    #pragma unroll
    for (int d = 0; d < 13; ++d){
      if (d < mdw){
        wr_[d] = Wf[( 0 + j)*13 + d];
        wz_[d] = Wf[( 8 + j)*13 + d];
        wn_[d] = Wf[(16 + j)*13 + d];
      } else { wr_[d] = 0.f; wz_[d] = 0.f; wn_[d] = 0.f; }
    }
  }
  float ur_[8], uz_[8], un_[8];
  {
    const float* Uf = Whh + f*24*8;
    #pragma unroll
    for (int k = 0; k < 8; ++k){
      ur_[k] = Uf[( 0 + j)*8 + k];
      uz_[k] = Uf[( 8 + j)*8 + k];
      un_[k] = Uf[(16 + j)*8 + k];
    }
  }
  const float br  = bih[f*24 +      j] + bhh[f*24 +      j];
  const float bz  = bih[f*24 +  8 + j] + bhh[f*24 +  8 + j];
  const float bxn = bih[f*24 + 16 + j];
  const float bhn = bhh[f*24 + 16 + j];

  // ---- x staging: cp.async double buffer, CHK timesteps per chunk ----
  auto stage = [&](int c, int buf){
    #pragma unroll
    for (int blx = 0; blx < BPC; ++blx){
      const float* src = x + ((size_t)(bg0 + blx)*TSTEPS + (size_t)c*CHK)*XDIM;
      uint32_t dst = (uint32_t)__cvta_generic_to_shared(&xs[buf][blx][0]);
      for (int i = tid; i < (CHK*XDIM)/4; i += NTHREADS)
        cp16(dst + (uint32_t)i*16u, src + i*4);
    }
  };

  stage(0, 0); asm volatile("cp.async.commit_group;" ::: "memory");
  stage(1, 1); asm volatile("cp.async.commit_group;" ::: "memory");

  float h = 0.f;
  float* outp = out + (((size_t)(bg0 + bl)*TSTEPS)*NFEAT + f)*HDIM + j;

  for (int c = 0; c < NCHK; ++c){
    asm volatile("cp.async.wait_group 1;" ::: "memory");
    __syncthreads();
    const float* xbase = &xs[c & 1][bl][startf];

    #pragma unroll 2
    for (int tl = 0; tl < CHK; ++tl){
      // gates_x (input projection), warp-uniform bound => no divergence
      const float* xp = xbase + tl*XDIM;
      float gr = br, gz = bz, gn = bxn;
      #pragma unroll
      for (int d = 0; d < 13; ++d){
        if (d >= mdw) break;
        float xv = xp[d];
        gr = fmaf(wr_[d], xv, gr);
        gz = fmaf(wz_[d], xv, gz);
        gn = fmaf(wn_[d], xv, gn);
      }
      // gates_h: 8-lane shuffle matvec
      float hr = 0.f, hz = 0.f, hn = bhn;
      #pragma unroll
      for (int k = 0; k < 8; ++k){
        float hk = __shfl_sync(0xFFFFFFFFu, h, k, 8);
        hr = fmaf(ur_[k], hk, hr);
        hz = fmaf(uz_[k], hk, hz);
        hn = fmaf(un_[k], hk, hn);
      }
      float er = __expf(-(gr + hr));
      float r  = __fdividef(1.f, 1.f + er);
      float ez = __expf(-(gz + hz));
      float z  = __fdividef(1.f, 1.f + ez);
      float a  = fmaf(r, hn, gn);
      float en = __expf(-2.f*a);
      float n  = __fdividef(1.f - en, 1.f + en);
      h = fmaf(z, h - n, n);                      // (1-z)*n + z*h
      if (wen) outp[(size_t)(c*CHK + tl)*(NFEAT*HDIM)] = h;
    }

    __syncthreads();                              // buffer free before restage
    if (c + 2 < NCHK) stage(c + 2, c & 1);
    asm volatile("cp.async.commit_group;" ::: "memory");
  }
}

extern "C" void kernel_launch(void* const* d_in, const int* in_sizes, int n_in,
                              void* d_out, int out_size)
{
  const float* x   = (const float*)d_in[0];
  const float* Wih = (const float*)d_in[1];
  const float* Whh = (const float*)d_in[2];
  const float* bih = (const float*)d_in[3];
  const float* bhh = (const float*)d_in[4];
  (void)in_sizes; (void)n_in; (void)out_size;
  mcgru_kernel<<<BSZ/BPC, NTHREADS>>>(x, Wih, Whh, bih, bhh, (float*)d_out);
}

// round 2
// speedup vs baseline: 2.1646x; 2.1646x over previous
#include <cuda_runtime.h>
#include <cstdint>
#include <cstddef>

#define NFEAT 17
#define HDIM 8
#define BSZ 256
#define TSTEPS 512
#define XDIM 59
#define CHK 32
#define NCHK (TSTEPS/CHK)
#define BPC 2
#define NTHREADS 288
#define ROWPAD (CHK*XDIM + 16)   // pad so xp[d] overreads stay in-array

// Chain-to-slot mapping. slot = warp*4 + group. Heavy-d features (f1..f4)
// are packed into warps 1 and 2 (SMSP1/SMSP2); SMSP0 (warps 0,4,8) gets only
// d=1 features so the 3-warp subpartition carries the lightest per-step load.
__device__ __constant__ int8_t c_slot_f[36] = {
   6, 6, 7, 7,   3, 2, 4, 1,   3, 2, 4, 1,   0, 0, 5, 5,
   8, 8, 9, 9,  12,12,13,13,  14,14,15,15,  16,16,16,16,  10,10,11,11};
__device__ __constant__ int8_t c_slot_b[36] = {
   0, 1, 0, 1,   0, 0, 0, 0,   1, 1, 1, 1,   0, 1, 0, 1,
   0, 1, 0, 1,   0, 1, 0, 1,   0, 1, 0, 1,   0, 1, 0, 1,   0, 1, 0, 1};
__device__ __constant__ int8_t c_slot_wr[36] = {
   1, 1, 1, 1,   1, 1, 1, 1,   1, 1, 1, 1,   1, 1, 1, 1,
   1, 1, 1, 1,   1, 1, 1, 1,   1, 1, 1, 1,   1, 1, 0, 0,   1, 1, 1, 1};
// per-warp max feature dim (warp-uniform gx loop bound; W_ih is zero-masked
// beyond each feature's true d so extra iterations are exact no-ops)
__device__ __constant__ int8_t c_warp_mdw[9] = {1,13,13,2,1,1,1,1,1};
// segment start offsets (cumsum of DIMS)
__device__ __constant__ int8_t c_start[17] =
  {0,2,10,22,35,47,48,49,50,51,52,53,54,55,56,57,58};

template<int N> struct IC { static constexpr int value = N; };

__device__ __forceinline__ void cp16(uint32_t s, const float* g){
  asm volatile("cp.async.ca.shared.global [%0], [%1], 16;" :: "r"(s), "l"(g) : "memory");
}

extern "C" __global__ void __launch_bounds__(NTHREADS, 1)
mcgru_kernel(const float* __restrict__ x,   const float* __restrict__ Wih,
             const float* __restrict__ Whh, const float* __restrict__ bih,
             const float* __restrict__ bhh, float* __restrict__ out)
{
  __shared__ __align__(16) float xs[2][BPC][ROWPAD];

  const int tid  = threadIdx.x;
  const int w    = tid >> 5;
  const int slot = tid >> 3;
  const int j    = tid & 7;
  const int f    = c_slot_f[slot];
  const int bl   = c_slot_b[slot];
  const bool wen = (bool)c_slot_wr[slot];
  const int mdw  = c_warp_mdw[w];
  const int startf = c_start[f];
  const int bg0  = blockIdx.x * BPC;

  // ---- per-thread weights in registers (rows j, 8+j, 16+j of feature f) ----
  float wr_[13], wz_[13], wn_[13];
  {
    const float* Wf = Wih + f*24*13;
    #pragma unroll
    for (int d = 0; d < 13; ++d){
      if (d < mdw){
        wr_[d] = Wf[( 0 + j)*13 + d];
        wz_[d] = Wf[( 8 + j)*13 + d];
        wn_[d] = Wf[(16 + j)*13 + d];
      } else { wr_[d] = 0.f; wz_[d] = 0.f; wn_[d] = 0.f; }
    }
  }
  float ur_[8], uz_[8], un_[8];
  {
    const float* Uf = Whh + f*24*8;
    #pragma unroll
    for (int k = 0; k < 8; ++k){
      ur_[k] = Uf[( 0 + j)*8 + k];
      uz_[k] = Uf[( 8 + j)*8 + k];
      un_[k] = Uf[(16 + j)*8 + k];
    }
  }
  const float br  = bih[f*24 +      j] + bhh[f*24 +      j];
  const float bz  = bih[f*24 +  8 + j] + bhh[f*24 +  8 + j];
  const float bxn = bih[f*24 + 16 + j];
  const float bhn = bhh[f*24 + 16 + j];

  // ---- x staging: cp.async double buffer, CHK timesteps per chunk ----
  auto stage = [&](int c, int buf){
    #pragma unroll
    for (int blx = 0; blx < BPC; ++blx){
      const float* src = x + ((size_t)(bg0 + blx)*TSTEPS + (size_t)c*CHK)*XDIM;
      uint32_t dst = (uint32_t)__cvta_generic_to_shared(&xs[buf][blx][0]);
      for (int i = tid; i < (CHK*XDIM)/4; i += NTHREADS)
        cp16(dst + (uint32_t)i*16u, src + i*4);
    }
  };

  stage(0, 0); asm volatile("cp.async.commit_group;" ::: "memory");
  stage(1, 1); asm volatile("cp.async.commit_group;" ::: "memory");

  float h = 0.f;
  float* outp = out + (((size_t)(bg0 + bl)*TSTEPS)*NFEAT + f)*HDIM + j;

  // One chunk of CHK timesteps; D is a compile-time trip count so the gx
  // loads fully unroll and batch (no serialized LDS->FMA->branch iterations).
  auto run_chunk = [&](auto Dc, const float* xbase, float* outc){
    constexpr int D = decltype(Dc)::value;
    #pragma unroll 4
    for (int tl = 0; tl < CHK; ++tl){
      const float* xp = xbase + tl*XDIM;
      // input projection: independent unrolled loads, 3 fma chains
      float gr = br, gz = bz, gn = bxn;
      #pragma unroll
      for (int d = 0; d < D; ++d){
        float xv = xp[d];
        gr = fmaf(wr_[d], xv, gr);
        gz = fmaf(wz_[d], xv, gz);
        gn = fmaf(wn_[d], xv, gn);
      }
      // gh: broadcast h across the 8-lane group, 2-way split fma chains
      float hk[8];
      #pragma unroll
      for (int k = 0; k < 8; ++k) hk[k] = __shfl_sync(0xFFFFFFFFu, h, k, 8);
      float hrA = 0.f, hrB = 0.f, hzA = 0.f, hzB = 0.f, hnA = bhn, hnB = 0.f;
      #pragma unroll
      for (int k = 0; k < 4; ++k){
        hrA = fmaf(ur_[k],   hk[k],   hrA);
        hrB = fmaf(ur_[k+4], hk[k+4], hrB);
        hzA = fmaf(uz_[k],   hk[k],   hzA);
        hzB = fmaf(uz_[k+4], hk[k+4], hzB);
        hnA = fmaf(un_[k],   hk[k],   hnA);
        hnB = fmaf(un_[k+4], hk[k+4], hnB);
      }
      float hr = hrA + hrB, hz = hzA + hzB, hn = hnA + hnB;

      float er = __expf(-(gr + hr));
      float r  = __fdividef(1.f, 1.f + er);
      float ez = __expf(-(gz + hz));
      float z  = __fdividef(1.f, 1.f + ez);
      float a  = fmaf(r, hn, gn);
      float en = __expf(-2.f*a);
      float n  = __fdividef(1.f - en, 1.f + en);
      h = fmaf(z, h - n, n);                      // (1-z)*n + z*h
      if (wen) outc[(size_t)tl*(NFEAT*HDIM)] = h;
    }
  };

  for (int c = 0; c < NCHK; ++c){
    asm volatile("cp.async.wait_group 1;" ::: "memory");
    __syncthreads();
    const float* xbase = &xs[c & 1][bl][startf];
    float* outc = outp + (size_t)c*CHK*(NFEAT*HDIM);

    // warp-uniform dispatch; barriers stay outside the divergent region
    if (mdw == 13)      run_chunk(IC<13>{}, xbase, outc);
    else if (mdw == 2)  run_chunk(IC<2>{},  xbase, outc);
    else                run_chunk(IC<1>{},  xbase, outc);

    __syncthreads();                              // buffer free before restage
    if (c + 2 < NCHK) stage(c + 2, c & 1);
    asm volatile("cp.async.commit_group;" ::: "memory");
  }
}

extern "C" void kernel_launch(void* const* d_in, const int* in_sizes, int n_in,
                              void* d_out, int out_size)
{
  const float* x   = (const float*)d_in[0];
  const float* Wih = (const float*)d_in[1];
  const float* Whh = (const float*)d_in[2];
  const float* bih = (const float*)d_in[3];
  const float* bhh = (const float*)d_in[4];
  (void)in_sizes; (void)n_in; (void)out_size;
  mcgru_kernel<<<BSZ/BPC, NTHREADS>>>(x, Wih, Whh, bih, bhh, (float*)d_out);
}

// round 3
// speedup vs baseline: 2.6826x; 1.2393x over previous
#include <cuda_runtime.h>
#include <cstdint>
#include <cstddef>

#define NFEAT 17
#define HDIM 8
#define BSZ 256
#define TSTEPS 512
#define XDIM 59
#define CHK 32
#define NCHK (TSTEPS/CHK)
#define BPC 2
#define NTHREADS 288
#define ROWPAD (CHK*XDIM + 16)   // pad so xp[d] overreads stay in-array

// Chain-to-slot mapping. slot = warp*4 + group. Heavy-d features packed into
// warps 1 and 2 (SMSP1/SMSP2); SMSP0 (warps 0,4,8) gets only d<=1 features.
__device__ __constant__ int8_t c_slot_f[36] = {
   6, 6, 7, 7,   3, 2, 4, 1,   3, 2, 4, 1,   0, 0, 5, 5,
   8, 8, 9, 9,  12,12,13,13,  14,14,15,15,  16,16,16,16,  10,10,11,11};
__device__ __constant__ int8_t c_slot_b[36] = {
   0, 1, 0, 1,   0, 0, 0, 0,   1, 1, 1, 1,   0, 1, 0, 1,
   0, 1, 0, 1,   0, 1, 0, 1,   0, 1, 0, 1,   0, 1, 0, 1,   0, 1, 0, 1};
__device__ __constant__ int8_t c_slot_wr[36] = {
   1, 1, 1, 1,   1, 1, 1, 1,   1, 1, 1, 1,   1, 1, 1, 1,
   1, 1, 1, 1,   1, 1, 1, 1,   1, 1, 1, 1,   1, 1, 0, 0,   1, 1, 1, 1};
__device__ __constant__ int8_t c_warp_mdw[9] = {1,13,13,2,1,1,1,1,1};
__device__ __constant__ int8_t c_start[17] =
  {0,2,10,22,35,47,48,49,50,51,52,53,54,55,56,57,58};

template<int N> struct IC { static constexpr int value = N; };

__device__ __forceinline__ void cp16(uint32_t s, const float* g){
  asm volatile("cp.async.ca.shared.global [%0], [%1], 16;" :: "r"(s), "l"(g) : "memory");
}
__device__ __forceinline__ float tanh_ap(float x){
  float y; asm("tanh.approx.f32 %0, %1;" : "=f"(y) : "f"(x)); return y;
}

extern "C" __global__ void __launch_bounds__(NTHREADS, 1)
mcgru_kernel(const float* __restrict__ x,   const float* __restrict__ Wih,
             const float* __restrict__ Whh, const float* __restrict__ bih,
             const float* __restrict__ bhh, float* __restrict__ out)
{
  __shared__ __align__(16) float xs[2][BPC][ROWPAD];

  const int tid  = threadIdx.x;
  const int w    = tid >> 5;
  const int slot = tid >> 3;
  const int j    = tid & 7;
  const int f    = c_slot_f[slot];
  const int bl   = c_slot_b[slot];
  const bool wen = (bool)c_slot_wr[slot];
  const int mdw  = c_warp_mdw[w];
  const int startf = c_start[f];
  const int bg0  = blockIdx.x * BPC;

  // ---- per-thread weights in registers.
  // r/z paths pre-scaled by 0.5 (sigmoid(x) = 0.5 + 0.5*tanh(x/2));
  // hh n-path pre-scaled by 0.5 (a = gn + hnh + tanh(xr_half)*hnh).
  float wr_[13], wz_[13], wn_[13];
  {
    const float* Wf = Wih + f*24*13;
    #pragma unroll
    for (int d = 0; d < 13; ++d){
      if (d < mdw){
        wr_[d] = 0.5f*Wf[( 0 + j)*13 + d];
        wz_[d] = 0.5f*Wf[( 8 + j)*13 + d];
        wn_[d] =      Wf[(16 + j)*13 + d];
      } else { wr_[d] = 0.f; wz_[d] = 0.f; wn_[d] = 0.f; }
    }
  }
  float ur_[8], uz_[8], un_[8];
  {
    const float* Uf = Whh + f*24*8;
    #pragma unroll
    for (int k = 0; k < 8; ++k){
      ur_[k] = 0.5f*Uf[( 0 + j)*8 + k];
      uz_[k] = 0.5f*Uf[( 8 + j)*8 + k];
      un_[k] = 0.5f*Uf[(16 + j)*8 + k];
    }
  }
  const float br  = 0.5f*(bih[f*24 +      j] + bhh[f*24 +      j]);
  const float bz  = 0.5f*(bih[f*24 +  8 + j] + bhh[f*24 +  8 + j]);
  const float bxn = bih[f*24 + 16 + j];
  const float bhn = 0.5f*bhh[f*24 + 16 + j];

  // ---- x staging: cp.async double buffer, CHK timesteps per chunk ----
  auto stage = [&](int c, int buf){
    #pragma unroll
    for (int blx = 0; blx < BPC; ++blx){
      const float* src = x + ((size_t)(bg0 + blx)*TSTEPS + (size_t)c*CHK)*XDIM;
      uint32_t dst = (uint32_t)__cvta_generic_to_shared(&xs[buf][blx][0]);
      for (int i = tid; i < (CHK*XDIM)/4; i += NTHREADS)
        cp16(dst + (uint32_t)i*16u, src + i*4);
    }
  };

  stage(0, 0); asm volatile("cp.async.commit_group;" ::: "memory");
  stage(1, 1); asm volatile("cp.async.commit_group;" ::: "memory");

  float h = 0.f;
  float* outp = out + (((size_t)(bg0 + bl)*TSTEPS)*NFEAT + f)*HDIM + j;

  auto run_chunk = [&](auto Dc, const float* xbase, float* outc){
    constexpr int D = decltype(Dc)::value;
    #pragma unroll 4
    for (int tl = 0; tl < CHK; ++tl){
      const float* xp = xbase + tl*XDIM;
      // input projection (r/z halves pre-folded into weights)
      float gr = br, gz = bz, gn = bxn;
      #pragma unroll
      for (int d = 0; d < D; ++d){
        float xv = xp[d];
        gr = fmaf(wr_[d], xv, gr);
        gz = fmaf(wz_[d], xv, gz);
        gn = fmaf(wn_[d], xv, gn);
      }
      // gh: broadcast h across the 8-lane group, 2-way split fma chains
      float hk[8];
      #pragma unroll
      for (int k = 0; k < 8; ++k) hk[k] = __shfl_sync(0xFFFFFFFFu, h, k, 8);
      float hrA = 0.f, hrB = 0.f, hzA = 0.f, hzB = 0.f, hnA = bhn, hnB = 0.f;
      #pragma unroll
      for (int k = 0; k < 4; ++k){
        hrA = fmaf(ur_[k],   hk[k],   hrA);
        hrB = fmaf(ur_[k+4], hk[k+4], hrB);
        hzA = fmaf(uz_[k],   hk[k],   hzA);
        hzB = fmaf(uz_[k+4], hk[k+4], hzB);
        hnA = fmaf(un_[k],   hk[k],   hnA);
        hnB = fmaf(un_[k+4], hk[k+4], hnB);
      }
      // tanh-form GRU: r = .5+.5*tr, z = .5+.5*tz
      float tr  = tanh_ap(gr + (hrA + hrB));      // arg already halved
      float tz  = tanh_ap(gz + (hzA + hzB));
      float hnh = hnA + hnB;                       // 0.5 * (Un h + bhn)
      float a   = fmaf(tr, hnh, gn + hnh);         // gn + r*(Un h + bhn)
      float n   = tanh_ap(a);
      float u   = 0.5f*(h - n);
      h = fmaf(tz, u, n + u);                      // (1-z)*n + z*h
      if (wen) outc[(size_t)tl*(NFEAT*HDIM)] = h;
    }
  };

  for (int c = 0; c < NCHK; ++c){
    asm volatile("cp.async.wait_group 1;" ::: "memory");
    __syncthreads();
    const float* xbase = &xs[c & 1][bl][startf];
    float* outc = outp + (size_t)c*CHK*(NFEAT*HDIM);

    if (mdw == 13)      run_chunk(IC<13>{}, xbase, outc);
    else if (mdw == 2)  run_chunk(IC<2>{},  xbase, outc);
    else                run_chunk(IC<1>{},  xbase, outc);

    __syncthreads();
    if (c + 2 < NCHK) stage(c + 2, c & 1);
    asm volatile("cp.async.commit_group;" ::: "memory");
  }
}

extern "C" void kernel_launch(void* const* d_in, const int* in_sizes, int n_in,
                              void* d_out, int out_size)
{
  const float* x   = (const float*)d_in[0];
  const float* Wih = (const float*)d_in[1];
  const float* Whh = (const float*)d_in[2];
  const float* bih = (const float*)d_in[3];
  const float* bhh = (const float*)d_in[4];
  (void)in_sizes; (void)n_in; (void)out_size;
  mcgru_kernel<<<BSZ/BPC, NTHREADS>>>(x, Wih, Whh, bih, bhh, (float*)d_out);
}

// round 4
// speedup vs baseline: 2.8406x; 1.0589x over previous
#include <cuda_runtime.h>
#include <cstdint>
#include <cstddef>

#define NFEAT 17
#define HDIM 8
#define BSZ 256
#define TSTEPS 512
#define XDIM 59
#define CHK 32
#define NCHK (TSTEPS/CHK)
#define BPC 2
#define NTHREADS 288
#define ROWPAD (CHK*XDIM + 16)   // pad so xp[d] overreads stay in-array

typedef unsigned long long u64;

// Chain-to-slot mapping. slot = warp*4 + group. Heavy warps d-homogeneous:
// w1={f3,f3,f2,f2} mdw13 (SMSP1), w2={f4,f4,f1,f1} mdw12 (SMSP2).
// SMSP0 (w0,w4,w8) and SMSP3 (w3,w7) carry only light features.
__device__ __constant__ int8_t c_slot_f[36] = {
   6, 6, 7, 7,   3, 3, 2, 2,   4, 4, 1, 1,   0, 0, 5, 5,
   8, 8, 9, 9,  10,10,11,11,  12,12,13,13,  14,14,15,15,  16,16,16,16};
__device__ __constant__ int8_t c_slot_b[36] = {
   0, 1, 0, 1,   0, 1, 0, 1,   0, 1, 0, 1,   0, 1, 0, 1,
   0, 1, 0, 1,   0, 1, 0, 1,   0, 1, 0, 1,   0, 1, 0, 1,   0, 1, 0, 1};
__device__ __constant__ int8_t c_slot_wr[36] = {
   1, 1, 1, 1,   1, 1, 1, 1,   1, 1, 1, 1,   1, 1, 1, 1,
   1, 1, 1, 1,   1, 1, 1, 1,   1, 1, 1, 1,   1, 1, 1, 1,   1, 1, 0, 0};
__device__ __constant__ int8_t c_warp_mdw[9] = {1,13,12,2,1,1,1,1,1};
__device__ __constant__ int8_t c_start[17] =
  {0,2,10,22,35,47,48,49,50,51,52,53,54,55,56,57,58};

template<int N> struct IC { static constexpr int value = N; };

__device__ __forceinline__ void cp16(uint32_t s, const float* g){
  asm volatile("cp.async.ca.shared.global [%0], [%1], 16;" :: "r"(s), "l"(g) : "memory");
}
__device__ __forceinline__ float tanh_ap(float x){
  float y; asm("tanh.approx.f32 %0, %1;" : "=f"(y) : "f"(x)); return y;
}
// ---- packed f32x2 helpers (Blackwell; ptxas never auto-fuses these) ----
__device__ __forceinline__ u64 pk(float lo, float hi){
  u64 r; asm("mov.b64 %0,{%1,%2};" : "=l"(r) : "f"(lo), "f"(hi)); return r;
}
__device__ __forceinline__ void upk(float& lo, float& hi, u64 p){
  asm("mov.b64 {%0,%1},%2;" : "=f"(lo), "=f"(hi) : "l"(p));
}
__device__ __forceinline__ u64 fma2(u64 a, u64 b, u64 c){
  u64 d; asm("fma.rn.f32x2 %0,%1,%2,%3;" : "=l"(d) : "l"(a), "l"(b), "l"(c)); return d;
}
__device__ __forceinline__ u64 add2(u64 a, u64 b){
  u64 d; asm("add.rn.f32x2 %0,%1,%2;" : "=l"(d) : "l"(a), "l"(b)); return d;
}

extern "C" __global__ void __launch_bounds__(NTHREADS, 1)
mcgru_kernel(const float* __restrict__ x,   const float* __restrict__ Wih,
             const float* __restrict__ Whh, const float* __restrict__ bih,
             const float* __restrict__ bhh, float* __restrict__ out)
{
  __shared__ __align__(16) float xs[2][BPC][ROWPAD];

  const int tid  = threadIdx.x;
  const int w    = tid >> 5;
  const int slot = tid >> 3;
  const int j    = tid & 7;
  const int f    = c_slot_f[slot];
  const int bl   = c_slot_b[slot];
  const bool wen = (bool)c_slot_wr[slot];
  const int mdw  = c_warp_mdw[w];
  const int startf = c_start[f];
  const int bg0  = blockIdx.x * BPC;

  // ---- weights in registers; (r,z) pairs packed as f32x2, pre-scaled by 0.5
  // (sigmoid(x) = 0.5 + 0.5*tanh(x/2)); hh n-path pre-scaled by 0.5.
  u64 wrz_[13]; float wn_[13];
  {
    const float* Wf = Wih + f*24*13;
    #pragma unroll
    for (int d = 0; d < 13; ++d){
      if (d < mdw){
        wrz_[d] = pk(0.5f*Wf[(0 + j)*13 + d], 0.5f*Wf[(8 + j)*13 + d]);
        wn_[d]  = Wf[(16 + j)*13 + d];
      } else { wrz_[d] = pk(0.f, 0.f); wn_[d] = 0.f; }
    }
  }
  u64 urz_[8]; float un_[8];
  {
    const float* Uf = Whh + f*24*8;
    #pragma unroll
    for (int k = 0; k < 8; ++k){
      urz_[k] = pk(0.5f*Uf[(0 + j)*8 + k], 0.5f*Uf[(8 + j)*8 + k]);
      un_[k]  = 0.5f*Uf[(16 + j)*8 + k];
    }
  }
  const u64 brz = pk(0.5f*(bih[f*24 + j]     + bhh[f*24 + j]),
                     0.5f*(bih[f*24 + 8 + j] + bhh[f*24 + 8 + j]));
  const float bxn = bih[f*24 + 16 + j];
  const float bhn = 0.5f*bhh[f*24 + 16 + j];

  // ---- x staging: cp.async double buffer, CHK timesteps per chunk ----
  auto stage = [&](int c, int buf){
    #pragma unroll
    for (int blx = 0; blx < BPC; ++blx){
      const float* src = x + ((size_t)(bg0 + blx)*TSTEPS + (size_t)c*CHK)*XDIM;
      uint32_t dst = (uint32_t)__cvta_generic_to_shared(&xs[buf][blx][0]);
      for (int i = tid; i < (CHK*XDIM)/4; i += NTHREADS)
        cp16(dst + (uint32_t)i*16u, src + i*4);
    }
  };

  stage(0, 0); asm volatile("cp.async.commit_group;" ::: "memory");
  stage(1, 1); asm volatile("cp.async.commit_group;" ::: "memory");

  float h = 0.f;
  float* outp = out + (((size_t)(bg0 + bl)*TSTEPS)*NFEAT + f)*HDIM + j;

  auto run_chunk = [&](auto Dc, const float* xbase, float* outc){
    constexpr int D = decltype(Dc)::value;
    #pragma unroll 4
    for (int tl = 0; tl < CHK; ++tl){
      const float* xp = xbase + tl*XDIM;
      // input projection: packed (r,z) chain + scalar n chain.
      // {xv,xv} packs land on the ALU pipe, off the saturated FMA pipe.
      u64 grz = brz; float gn = bxn;
      #pragma unroll
      for (int d = 0; d < D; ++d){
        float xv = xp[d];
        grz = fma2(wrz_[d], pk(xv, xv), grz);
        gn  = fmaf(wn_[d], xv, gn);
      }
      // gh: broadcast h across the 8-lane group; packed (r,z), split n
      float hk[8];
      #pragma unroll
      for (int k = 0; k < 8; ++k) hk[k] = __shfl_sync(0xFFFFFFFFu, h, k, 8);
      u64 hrz0 = pk(0.f, 0.f), hrz1 = pk(0.f, 0.f);
      float hnA = bhn, hnB = 0.f;
      #pragma unroll
      for (int k = 0; k < 4; ++k){
        hrz0 = fma2(urz_[k],   pk(hk[k],   hk[k]),   hrz0);
        hrz1 = fma2(urz_[k+4], pk(hk[k+4], hk[k+4]), hrz1);
        hnA  = fmaf(un_[k],   hk[k],   hnA);
        hnB  = fmaf(un_[k+4], hk[k+4], hnB);
      }
      u64 arz = add2(grz, add2(hrz0, hrz1));
      float ar, az; upk(ar, az, arz);
      // tanh-form GRU: r = .5+.5*tr, z = .5+.5*tz (halves folded into weights)
      float tr  = tanh_ap(ar);
      float tz  = tanh_ap(az);
      float hnh = hnA + hnB;                       // 0.5 * (Un h + bhn)
      float a   = fmaf(tr, hnh, gn + hnh);         // gn + r*(Un h + bhn)
      float n   = tanh_ap(a);
      float u   = 0.5f*(h - n);
      h = fmaf(tz, u, n + u);                      // (1-z)*n + z*h
      if (wen) outc[(size_t)tl*(NFEAT*HDIM)] = h;
    }
  };

  for (int c = 0; c < NCHK; ++c){
    asm volatile("cp.async.wait_group 1;" ::: "memory");
    __syncthreads();
    const float* xbase = &xs[c & 1][bl][startf];
    float* outc = outp + (size_t)c*CHK*(NFEAT*HDIM);

    if (mdw == 13)      run_chunk(IC<13>{}, xbase, outc);
    else if (mdw == 12) run_chunk(IC<12>{}, xbase, outc);
    else if (mdw == 2)  run_chunk(IC<2>{},  xbase, outc);
    else                run_chunk(IC<1>{},  xbase, outc);

    __syncthreads();
    if (c + 2 < NCHK) stage(c + 2, c & 1);
    asm volatile("cp.async.commit_group;" ::: "memory");
  }
}

extern "C" void kernel_launch(void* const* d_in, const int* in_sizes, int n_in,
                              void* d_out, int out_size)
{
  const float* x   = (const float*)d_in[0];
  const float* Wih = (const float*)d_in[1];
  const float* Whh = (const float*)d_in[2];
  const float* bih = (const float*)d_in[3];
  const float* bhh = (const float*)d_in[4];
  (void)in_sizes; (void)n_in; (void)out_size;
  mcgru_kernel<<<BSZ/BPC, NTHREADS>>>(x, Wih, Whh, bih, bhh, (float*)d_out);
}